// round 1
// baseline (speedup 1.0000x reference)
#include <cuda_runtime.h>

// Problem shape (fixed by dataset): N=25000 nodes, E=400000 edges, D=32.
// out[i,h] = sum_{e: dst_e=i} msgs[e,h] + sum_d x[i,d]*node_W[h,d]
// msgs[e,h] = sum_k edge_attr[e,k] * Y[src_e, k*32+h]
// Y[j, k*32+h] = sum_d x[j,d] * W2[d, k*32+h],  W2[d, k*32+h] = edge_W[(d*32+h)*32 + k]

#define DD 32
#define N_MAX 25000
#define KH 1024   // D*D

// Scratch (static device allocations are allowed; cudaMalloc is not)
__device__ float g_Y[(size_t)N_MAX * KH];   // 102.4 MB
__device__ float g_W2[DD * KH];             // 128 KB

// ---------------------------------------------------------------------------
// Kernel 1: reorder edge_W [1024,32] -> W2 [32,1024] with W2[d][k*32+h] = eW[(d*32+h)*32+k]
// ---------------------------------------------------------------------------
__global__ void reorder_w_kernel(const float* __restrict__ edge_W) {
    int idx = blockIdx.x * blockDim.x + threadIdx.x;
    if (idx < DD * KH) {
        int d  = idx >> 10;
        int kh = idx & (KH - 1);
        int k  = kh >> 5;
        int h  = kh & 31;
        g_W2[idx] = edge_W[(d * 32 + h) * 32 + k];
    }
}

// ---------------------------------------------------------------------------
// Kernel 2: out[i,h] = sum_d x[i,d] * node_W[h,d]   (initializes the output;
// the edge kernel then atomically accumulates messages on top)
// ---------------------------------------------------------------------------
__global__ void node_init_kernel(const float* __restrict__ x,
                                 const float* __restrict__ node_W,
                                 float* __restrict__ out, int N) {
    __shared__ float sWT[DD * DD];   // transposed: sWT[d*32+h] = node_W[h*32+d]
    __shared__ float sx[8][DD];
    int t = threadIdx.x;             // 256 threads
    for (int i = t; i < DD * DD; i += 256) {
        int h = i & 31, d = i >> 5;
        sWT[d * 32 + h] = node_W[h * 32 + d];
    }
    int node0 = blockIdx.x * 8;
    int r = t >> 5, h = t & 31;
    int node = node0 + r;
    if (node < N) sx[r][h] = x[node * DD + h];
    __syncthreads();
    if (node < N) {
        float acc = 0.f;
        #pragma unroll
        for (int d = 0; d < DD; d++) acc += sx[r][d] * sWT[d * 32 + h];
        out[node * DD + h] = acc;
    }
}

// ---------------------------------------------------------------------------
// Kernel 3: Y = x @ W2   ([N,32] @ [32,1024] -> [N,1024])
// grid: (4, ceil(N/32)); block: 256. Each thread owns one output column for
// a 32-row tile; weights for that column held in 32 registers.
// ---------------------------------------------------------------------------
__global__ void y_gemm_kernel(const float* __restrict__ x, int N) {
    __shared__ float sx[32][DD + 1];
    int tx = threadIdx.x;                 // 0..255
    int c  = blockIdx.x * 256 + tx;       // column in [0,1024)
    int r0 = blockIdx.y * 32;

    for (int i = tx; i < 32 * DD; i += 256) {
        int r = i >> 5, d = i & 31;
        sx[r][d] = (r0 + r < N) ? x[(r0 + r) * DD + d] : 0.f;
    }
    __syncthreads();

    float w[DD];
    #pragma unroll
    for (int d = 0; d < DD; d++) w[d] = g_W2[d * KH + c];

    int rmax = N - r0; if (rmax > 32) rmax = 32;
    for (int r = 0; r < rmax; r++) {
        float a0 = 0.f, a1 = 0.f, a2 = 0.f, a3 = 0.f;
        #pragma unroll
        for (int d = 0; d < DD; d += 4) {
            a0 += sx[r][d + 0] * w[d + 0];
            a1 += sx[r][d + 1] * w[d + 1];
            a2 += sx[r][d + 2] * w[d + 2];
            a3 += sx[r][d + 3] * w[d + 3];
        }
        g_Y[(size_t)(r0 + r) * KH + c] = (a0 + a1) + (a2 + a3);
    }
}

// ---------------------------------------------------------------------------
// Kernel 4: per-edge message + scatter-add. One warp per edge.
// lane = output channel h. msgs[h] = sum_k ea[k] * Y[src][k*32+h]
// Loads are warp-coalesced 128B lines (Y row base is 128B-aligned).
// ---------------------------------------------------------------------------
__global__ void edge_kernel(const float* __restrict__ edge_attr,
                            const int*   __restrict__ edge_index,
                            float* __restrict__ out, int E) {
    int gwarp = (blockIdx.x * blockDim.x + threadIdx.x) >> 5;
    int lane  = threadIdx.x & 31;
    if (gwarp >= E) return;   // warp-uniform exit

    int src = edge_index[gwarp];
    int dst = edge_index[E + gwarp];
    float ea = edge_attr[(size_t)gwarp * DD + lane];
    const float* y = g_Y + (size_t)src * KH;

    // Batch all 32 row loads first for maximum MLP into L2.
    float yv[32];
    #pragma unroll
    for (int k = 0; k < 32; k++) yv[k] = y[k * 32 + lane];

    float a0 = 0.f, a1 = 0.f, a2 = 0.f, a3 = 0.f;
    #pragma unroll
    for (int k = 0; k < 32; k += 4) {
        a0 += __shfl_sync(0xffffffffu, ea, k + 0) * yv[k + 0];
        a1 += __shfl_sync(0xffffffffu, ea, k + 1) * yv[k + 1];
        a2 += __shfl_sync(0xffffffffu, ea, k + 2) * yv[k + 2];
        a3 += __shfl_sync(0xffffffffu, ea, k + 3) * yv[k + 3];
    }
    atomicAdd(&out[(size_t)dst * DD + lane], (a0 + a1) + (a2 + a3));
}

// ---------------------------------------------------------------------------
// Launch
// inputs: 0: x [N*32] f32, 1: edge_attr [E*32] f32, 2: edge_W [1024*32] f32,
//         3: node_W [32*32] f32, 4: edge_index [2*E] i32.  out: [N*32] f32
// ---------------------------------------------------------------------------
extern "C" void kernel_launch(void* const* d_in, const int* in_sizes, int n_in,
                              void* d_out, int out_size) {
    const float* x         = (const float*)d_in[0];
    const float* edge_attr = (const float*)d_in[1];
    const float* edge_W    = (const float*)d_in[2];
    const float* node_W    = (const float*)d_in[3];
    const int*   edge_idx  = (const int*)  d_in[4];
    float* out = (float*)d_out;

    int N = in_sizes[0] / DD;
    int E = in_sizes[4] / 2;
    if (N > N_MAX) N = N_MAX;   // g_Y capacity guard (shape is fixed at 25000)

    // 1. reorder weights
    reorder_w_kernel<<<(DD * KH + 255) / 256, 256>>>(edge_W);

    // 2. init output with node MLP term
    node_init_kernel<<<(N + 7) / 8, 256>>>(x, node_W, out, N);

    // 3. Y = x @ W2
    dim3 ygrid(KH / 256, (N + 31) / 32);
    y_gemm_kernel<<<ygrid, 256>>>(x, N);

    // 4. edge messages + scatter
    int warpsPerBlock = 8;
    int blocks = (E + warpsPerBlock - 1) / warpsPerBlock;
    edge_kernel<<<blocks, warpsPerBlock * 32>>>(edge_attr, edge_idx, out, E);
}

// round 2
// speedup vs baseline: 1.2084x; 1.2084x over previous
#include <cuda_runtime.h>

// N=25000 nodes, E=400000 edges, D=32.
// out[i,h] = sum_{e: dst_e=i} msgs[e,h] + sum_d x[i,d]*node_W[h,d]
// msgs[e,h] = sum_k edge_attr[e,k] * Y[src_e, k*32+h]
// Y[j, k*32+h] = sum_d x[j,d] * W2[d, k*32+h],  W2[d, k*32+h] = edge_W[(d*32+h)*32 + k]

#define DD 32
#define N_MAX 25000
#define E_MAX 400000
#define KH 1024   // D*D

// Static device scratch (no dynamic allocation allowed)
__device__ float g_Y[(size_t)N_MAX * KH];   // 102.4 MB
__device__ float g_W2[DD * KH];             // 128 KB
__device__ int   g_hist[N_MAX];
__device__ int   g_cursor[N_MAX];
__device__ int   g_perm[E_MAX];
__device__ int   g_ssorted[E_MAX];
__device__ int   g_dsorted[E_MAX];

// ---------------------------------------------------------------------------
// Kernel: reorder edge_W [1024,32] -> W2 [32,1024];  also zero histogram.
// ---------------------------------------------------------------------------
__global__ void reorder_w_kernel(const float* __restrict__ edge_W, int N) {
    int idx = blockIdx.x * blockDim.x + threadIdx.x;
    if (idx < DD * KH) {
        int d  = idx >> 10;
        int kh = idx & (KH - 1);
        int k  = kh >> 5;
        int h  = kh & 31;
        g_W2[idx] = edge_W[(d * 32 + h) * 32 + k];
    }
    if (idx < N) g_hist[idx] = 0;
}

// ---------------------------------------------------------------------------
// Kernel: histogram of src
// ---------------------------------------------------------------------------
__global__ void hist_kernel(const int* __restrict__ edge_index, int E) {
    int e = blockIdx.x * blockDim.x + threadIdx.x;
    if (e < E) atomicAdd(&g_hist[edge_index[e]], 1);
}

// ---------------------------------------------------------------------------
// Kernel: single-block exclusive scan of g_hist[0..N) -> g_cursor (scatter
// cursors). 1024 threads, Hillis-Steele per 1024-chunk with running offset.
// ---------------------------------------------------------------------------
__global__ void scan_kernel(int N) {
    __shared__ int tmp[1024];
    __shared__ int running;
    int t = threadIdx.x;
    if (t == 0) running = 0;
    __syncthreads();
    for (int base = 0; base < N; base += 1024) {
        int i = base + t;
        int v = (i < N) ? g_hist[i] : 0;
        tmp[t] = v;
        __syncthreads();
        for (int off = 1; off < 1024; off <<= 1) {
            int add = (t >= off) ? tmp[t - off] : 0;
            __syncthreads();
            tmp[t] += add;
            __syncthreads();
        }
        int excl = tmp[t] - v;
        int run = running;
        if (i < N) g_cursor[i] = run + excl;
        __syncthreads();
        if (t == 0) running += tmp[1023];
        __syncthreads();
    }
}

// ---------------------------------------------------------------------------
// Kernel: scatter edges into src-sorted order
// ---------------------------------------------------------------------------
__global__ void scatter_kernel(const int* __restrict__ edge_index, int E) {
    int e = blockIdx.x * blockDim.x + threadIdx.x;
    if (e < E) {
        int s = edge_index[e];
        int pos = atomicAdd(&g_cursor[s], 1);
        g_perm[pos]    = e;
        g_ssorted[pos] = s;
        g_dsorted[pos] = edge_index[E + e];
    }
}

// ---------------------------------------------------------------------------
// Kernel: out[i,h] = sum_d x[i,d] * node_W[h,d]
// ---------------------------------------------------------------------------
__global__ void node_init_kernel(const float* __restrict__ x,
                                 const float* __restrict__ node_W,
                                 float* __restrict__ out, int N) {
    __shared__ float sWT[DD * DD];   // sWT[d*32+h] = node_W[h*32+d]
    __shared__ float sx[8][DD];
    int t = threadIdx.x;             // 256 threads
    for (int i = t; i < DD * DD; i += 256) {
        int h = i & 31, d = i >> 5;
        sWT[d * 32 + h] = node_W[h * 32 + d];
    }
    int node0 = blockIdx.x * 8;
    int r = t >> 5, h = t & 31;
    int node = node0 + r;
    if (node < N) sx[r][h] = x[node * DD + h];
    __syncthreads();
    if (node < N) {
        float acc = 0.f;
        #pragma unroll
        for (int d = 0; d < DD; d++) acc += sx[r][d] * sWT[d * 32 + h];
        out[node * DD + h] = acc;
    }
}

// ---------------------------------------------------------------------------
// Kernel: Y = x @ W2   ([N,32] @ [32,1024]). float4 smem reads to cut LDS 4x.
// ---------------------------------------------------------------------------
__global__ void y_gemm_kernel(const float* __restrict__ x, int N) {
    __shared__ float4 sx4[32][9];   // 8 used + pad
    int tx = threadIdx.x;                 // 0..255
    int c  = blockIdx.x * 256 + tx;       // column in [0,1024)
    int r0 = blockIdx.y * 32;

    for (int i = tx; i < 32 * 8; i += 256) {
        int r = i >> 3, j = i & 7;
        float4 v = make_float4(0.f, 0.f, 0.f, 0.f);
        if (r0 + r < N) v = ((const float4*)x)[(size_t)(r0 + r) * 8 + j];
        sx4[r][j] = v;
    }
    __syncthreads();

    float w[DD];
    #pragma unroll
    for (int d = 0; d < DD; d++) w[d] = g_W2[d * KH + c];

    int rmax = N - r0; if (rmax > 32) rmax = 32;
    for (int r = 0; r < rmax; r++) {
        float a0 = 0.f, a1 = 0.f, a2 = 0.f, a3 = 0.f;
        #pragma unroll
        for (int j = 0; j < 8; j++) {
            float4 v = sx4[r][j];
            a0 += v.x * w[4 * j + 0];
            a1 += v.y * w[4 * j + 1];
            a2 += v.z * w[4 * j + 2];
            a3 += v.w * w[4 * j + 3];
        }
        g_Y[(size_t)(r0 + r) * KH + c] = (a0 + a1) + (a2 + a3);
    }
}

// ---------------------------------------------------------------------------
// Kernel: sorted edge messages. One warp per 8 consecutive sorted edges;
// Y row cached in registers across a same-src run. lane = channel h.
// ---------------------------------------------------------------------------
__global__ void edge_sorted_kernel(const float* __restrict__ edge_attr,
                                   float* __restrict__ out, int E) {
    int w    = (blockIdx.x * blockDim.x + threadIdx.x) >> 5;
    int lane = threadIdx.x & 31;
    int e0 = w * 8;
    if (e0 >= E) return;   // warp-uniform
    int cnt = E - e0; if (cnt > 8) cnt = 8;

    float yv[32];
    int prev = -1;
    for (int i = 0; i < cnt; i++) {
        int e = e0 + i;
        int s = g_ssorted[e];        // warp-uniform broadcast load
        if (s != prev) {
            const float* y = g_Y + (size_t)s * KH;
            #pragma unroll
            for (int k = 0; k < 32; k++) yv[k] = y[k * 32 + lane];
            prev = s;
        }
        float ea = edge_attr[(size_t)g_perm[e] * DD + lane];
        float a0 = 0.f, a1 = 0.f, a2 = 0.f, a3 = 0.f;
        #pragma unroll
        for (int k = 0; k < 32; k += 4) {
            a0 += __shfl_sync(0xffffffffu, ea, k + 0) * yv[k + 0];
            a1 += __shfl_sync(0xffffffffu, ea, k + 1) * yv[k + 1];
            a2 += __shfl_sync(0xffffffffu, ea, k + 2) * yv[k + 2];
            a3 += __shfl_sync(0xffffffffu, ea, k + 3) * yv[k + 3];
        }
        atomicAdd(&out[(size_t)g_dsorted[e] * DD + lane], (a0 + a1) + (a2 + a3));
    }
}

// ---------------------------------------------------------------------------
// Launch.  inputs: 0:x[N*32] 1:edge_attr[E*32] 2:edge_W[1024*32] 3:node_W[32*32]
//          4:edge_index[2*E] i32.  out: [N*32] f32
// ---------------------------------------------------------------------------
extern "C" void kernel_launch(void* const* d_in, const int* in_sizes, int n_in,
                              void* d_out, int out_size) {
    const float* x         = (const float*)d_in[0];
    const float* edge_attr = (const float*)d_in[1];
    const float* edge_W    = (const float*)d_in[2];
    const float* node_W    = (const float*)d_in[3];
    const int*   edge_idx  = (const int*)  d_in[4];
    float* out = (float*)d_out;

    int N = in_sizes[0] / DD;
    int E = in_sizes[4] / 2;
    if (N > N_MAX) N = N_MAX;
    if (E > E_MAX) E = E_MAX;

    // 1. weight reorder + histogram zero
    reorder_w_kernel<<<(DD * KH + 255) / 256, 256>>>(edge_W, N);

    // 2. counting sort of edges by src
    hist_kernel<<<(E + 255) / 256, 256>>>(edge_idx, E);
    scan_kernel<<<1, 1024>>>(N);
    scatter_kernel<<<(E + 255) / 256, 256>>>(edge_idx, E);

    // 3. init output with node MLP term
    node_init_kernel<<<(N + 7) / 8, 256>>>(x, node_W, out, N);

    // 4. Y = x @ W2
    dim3 ygrid(KH / 256, (N + 31) / 32);
    y_gemm_kernel<<<ygrid, 256>>>(x, N);

    // 5. sorted edge messages + scatter
    int nwarps = (E + 7) / 8;
    int blocks = (nwarps * 32 + 255) / 256;
    edge_sorted_kernel<<<blocks, 256>>>(edge_attr, out, E);
}